// round 4
// baseline (speedup 1.0000x reference)
#include <cuda_runtime.h>
#include <math.h>

#define B_  32
#define N_  512
#define L_  12
#define U_  64
#define HOR 12

// ---------------------------------------------------------------------------
// Scratch layout (floats)
// ---------------------------------------------------------------------------
constexpr long SZ_NN = (long)B_ * N_ * N_;        // 8388608
constexpr long SZ_T  = (long)B_ * 4 * N_ * U_;    // 4194304
constexpr long SZ_H  = (long)B_ * N_ * U_;        // 1048576

constexpr long OFF_A0   = 0;
constexpr long OFF_A1   = OFF_A0 + SZ_NN;
constexpr long OFF_P    = OFF_A1 + SZ_NN;           // (B, 4*512, 512)
constexpr long OFF_TCAT = OFF_P + 4 * SZ_NN;        // (B, 2048, 128) merged; layer0: TXIN here
constexpr long OFF_THX  = OFF_TCAT + SZ_T;          // layer0 THX (B,2048,64); also TCAT upper half
constexpr long OFF_TRHX = OFF_THX + SZ_T;           // (B, 2048, 64)
constexpr long OFF_RHX  = OFF_TRHX + SZ_T;
constexpr long OFF_U    = OFF_RHX + SZ_H;
constexpr long OFF_H0   = OFF_U + SZ_H;
constexpr long OFF_H1   = OFF_H0 + SZ_H;
constexpr long OFF_H2   = OFF_H1 + SZ_H;
constexpr long OFF_H3   = OFF_H2 + SZ_H;
constexpr long OFF_HIS  = OFF_H3 + SZ_H;
constexpr long OFF_FC1  = OFF_HIS + SZ_H;           // (16384, 256)
constexpr long OFF_DEC  = OFF_FC1 + (long)B_ * N_ * 256;
constexpr long OFF_RS0  = OFF_DEC + (long)B_ * N_;
constexpr long OFF_RS1  = OFF_RS0 + (long)B_ * N_;
constexpr long SCRATCH_TOTAL = OFF_RS1 + (long)B_ * N_;

__device__ float g_scratch[SCRATCH_TOTAL];

// ---------------------------------------------------------------------------
// Packed f32x2 FMA helpers
// ---------------------------------------------------------------------------
__device__ __forceinline__ void ffma2(unsigned long long& d,
                                      unsigned long long a,
                                      unsigned long long b) {
    asm("fma.rn.f32x2 %0, %1, %2, %0;" : "+l"(d) : "l"(a), "l"(b));
}
__device__ __forceinline__ float f2lo(unsigned long long v) {
    return __uint_as_float((unsigned)(v & 0xffffffffull));
}
__device__ __forceinline__ float f2hi(unsigned long long v) {
    return __uint_as_float((unsigned)(v >> 32));
}

// ---------------------------------------------------------------------------
// Support construction
// ---------------------------------------------------------------------------
__global__ void rowsum_k(const float* __restrict__ adj, float* __restrict__ rs0) {
    int w = (blockIdx.x * blockDim.x + threadIdx.x) >> 5;
    int lane = threadIdx.x & 31;
    if (w >= B_ * N_) return;
    const float* base = adj + (long)w * N_;
    float s = 0.f;
    for (int j = lane; j < N_; j += 32) s += base[j];
    #pragma unroll
    for (int o = 16; o; o >>= 1) s += __shfl_xor_sync(0xffffffffu, s, o);
    if (lane == 0) rs0[w] = s + 1.0f;
}

__global__ void colsum_k(const float* __restrict__ adj, float* __restrict__ rs1) {
    int idx = blockIdx.x * blockDim.x + threadIdx.x;
    if (idx >= B_ * N_) return;
    int b = idx >> 9, i = idx & 511;
    const float* base = adj + (long)b * N_ * N_ + i;
    float s = 1.0f;
    for (int j = 0; j < N_; j++) s += base[(long)j * N_];
    rs1[idx] = s;
}

__global__ void fill_supports(const float* __restrict__ adj,
                              const float* __restrict__ rs0,
                              const float* __restrict__ rs1,
                              float* __restrict__ A0, float* __restrict__ A1,
                              float* __restrict__ P) {
    long idx = (long)blockIdx.x * blockDim.x + threadIdx.x;
    if (idx >= (long)B_ * N_ * N_) return;
    int j = (int)(idx & 511);
    long t = idx >> 9;
    int i = (int)(t & 511);
    int b = (int)(t >> 9);
    float d = (i == j) ? 1.f : 0.f;
    float a = adj[idx];
    float v0 = (a + d) / rs0[b * N_ + i];
    A0[idx] = v0;
    P[(long)b * 4 * N_ * N_ + (long)i * N_ + j] = v0;   // block m=1: A0
    float at = adj[((long)b * N_ + j) * N_ + i];
    A1[idx] = (at + d) / rs1[b * N_ + i];
}

// ---------------------------------------------------------------------------
// Batched SGEMM with packed f32x2 FMA inner loop, dual-source B gather.
//   C[b] = A[b] @ Beff[b]; Beff col c: c<bsplit -> B1, else B2 (col c-bsplit).
// Requirements: M % BM == 0 (gridDim.y*BM == M), Ncols % BN == 0, K guarded.
// epi: 0 none, 1: 2x - I, 2: 2x - extra[b], 3: bias + relu
// ---------------------------------------------------------------------------
template<int BM, int BN, int TM, int TN>
__global__ __launch_bounds__(256, 2)
void sgemm2_t(int K,
              const float* __restrict__ A, int lda, long sA,
              const float* __restrict__ B1, int ldb1, long sB1,
              const float* __restrict__ B2, int ldb2, long sB2, int bsplit,
              float* __restrict__ C, int ldc, long sC,
              int epi, const float* __restrict__ extra, long sE,
              const float* __restrict__ bias)
{
    constexpr int BK = 16;
    constexpr int TX = BN / TN;            // threads along N
    constexpr int AE = BM * BK / 256;      // A elems per thread (consecutive k)
    constexpr int BF = BK * BN / 1024;     // B float4s per thread
    static_assert((BM / TM) * TX == 256, "thread count");

    __shared__ float As[2][BK][BM + 4];
    __shared__ float BsD[2][BK][2 * BN];

    int bz = blockIdx.z;
    const float* Ab = A + (long)bz * sA;
    float* Cb = C + (long)bz * sC;
    int row0 = blockIdx.y * BM, col0 = blockIdx.x * BN;
    int tid = threadIdx.x;
    int tx = tid % TX, ty = tid / TX;

    int am = tid % BM;
    int ak0 = (tid / BM) * AE;
    int bRow[BF], bCol[BF];
    #pragma unroll
    for (int s = 0; s < BF; s++) {
        int idx = tid + s * 256;
        bRow[s] = idx / (BN / 4);
        bCol[s] = (idx % (BN / 4)) << 2;
    }

    float aR[AE];
    float4 bR[BF];

    auto ldT = [&](int k0) {
        const float* pa = Ab + (long)(row0 + am) * lda + k0 + ak0;
        if (k0 + BK <= K) {
            #pragma unroll
            for (int e = 0; e < AE; e += 4) *(float4*)&aR[e] = *(const float4*)(pa + e);
        } else {
            #pragma unroll
            for (int e = 0; e < AE; e++) aR[e] = (k0 + ak0 + e < K) ? pa[e] : 0.f;
        }
        #pragma unroll
        for (int s = 0; s < BF; s++) {
            int k = k0 + bRow[s];
            int c = col0 + bCol[s];
            float4 v = make_float4(0.f, 0.f, 0.f, 0.f);
            if (k < K) {
                const float* p = (c < bsplit)
                    ? (B1 + (long)bz * sB1 + (long)k * ldb1 + c)
                    : (B2 + (long)bz * sB2 + (long)k * ldb2 + (c - bsplit));
                v = *(const float4*)p;
            }
            bR[s] = v;
        }
    };
    auto stT = [&](int buf) {
        #pragma unroll
        for (int e = 0; e < AE; e++) As[buf][ak0 + e][am] = aR[e];
        #pragma unroll
        for (int s = 0; s < BF; s++) {
            float4 v = bR[s];
            float4 lo = make_float4(v.x, v.x, v.y, v.y);
            float4 hi = make_float4(v.z, v.z, v.w, v.w);
            *(float4*)&BsD[buf][bRow[s]][2 * bCol[s]]     = lo;
            *(float4*)&BsD[buf][bRow[s]][2 * bCol[s] + 4] = hi;
        }
    };

    unsigned long long acc[TM / 2][TN];
    #pragma unroll
    for (int i = 0; i < TM / 2; i++)
        #pragma unroll
        for (int j = 0; j < TN; j++) acc[i][j] = 0ull;

    int ntile = (K + BK - 1) / BK;
    ldT(0); stT(0); __syncthreads();
    for (int t = 0; t < ntile; t++) {
        if (t + 1 < ntile) ldT((t + 1) * BK);
        int buf = t & 1;
        #pragma unroll
        for (int kk = 0; kk < BK; kk++) {
            unsigned long long a2[TM / 2], b2[TN];
            const unsigned long long* ap =
                (const unsigned long long*)&As[buf][kk][ty * TM];
            const unsigned long long* bp =
                (const unsigned long long*)&BsD[buf][kk][2 * tx * TN];
            #pragma unroll
            for (int i = 0; i < TM / 2; i++) a2[i] = ap[i];
            #pragma unroll
            for (int j = 0; j < TN; j++) b2[j] = bp[j];
            #pragma unroll
            for (int i = 0; i < TM / 2; i++)
                #pragma unroll
                for (int j = 0; j < TN; j++) ffma2(acc[i][j], a2[i], b2[j]);
        }
        if (t + 1 < ntile) stT(buf ^ 1);
        __syncthreads();
    }

    #pragma unroll
    for (int i = 0; i < TM / 2; i++) {
        #pragma unroll
        for (int half = 0; half < 2; half++) {
            int r = row0 + ty * TM + 2 * i + half;
            #pragma unroll
            for (int j = 0; j < TN; j++) {
                int c = col0 + tx * TN + j;
                float v = half ? f2hi(acc[i][j]) : f2lo(acc[i][j]);
                if (epi == 1) v = 2.f * v - ((r == c) ? 1.f : 0.f);
                else if (epi == 2) v = 2.f * v - extra[(long)bz * sE + (long)r * N_ + c];
                else if (epi == 3) { v += bias[c]; v = fmaxf(v, 0.f); }
                Cb[(long)r * ldc + c] = v;
            }
        }
    }
}

// ---------------------------------------------------------------------------
// Contraction GEMM over virtual concatenated diffusion terms.
// A_eff[row=(b,n), k=j*5+m]:
//   m==0: j<f_in -> Xa[b*sb + n*sn + j]      else Xb[row*64 + (j-f_in)]
//   m>=1: trow=b*2048+(m-1)*512+n
//         j<f_in -> Ta[trow*ldTa + j]        else Tb[trow*ldTb + (j-f_in)]
// mode 0: gate (sigmoid -> RHX/U). mode 1: cand (tanh -> GRU combine)
// ---------------------------------------------------------------------------
template<int BM, int BN, int TM, int TN>
__global__ __launch_bounds__(256, 2)
void catgemm2_t(int K, int f_in,
                const float* __restrict__ Xa, long sb, int sn,
                const float* __restrict__ Xb,
                const float* __restrict__ Ta, int ldTa,
                const float* __restrict__ Tb, int ldTb,
                const float* __restrict__ W, int ldW,
                const float* __restrict__ bias,
                const float* __restrict__ HX,
                float* __restrict__ RHX, float* __restrict__ Ubuf,
                float* __restrict__ Hout, int mode)
{
    constexpr int BK = 16;
    constexpr int TX = BN / TN;
    constexpr int AE = BM * BK / 256;
    constexpr int BF = BK * BN / 1024;
    static_assert((BM / TM) * TX == 256, "thread count");

    __shared__ float As[2][BK][BM + 4];
    __shared__ float BsD[2][BK][2 * BN];

    int row0 = blockIdx.y * BM;
    int col0 = blockIdx.x * BN;
    int tid = threadIdx.x;
    int tx = tid % TX, ty = tid / TX;

    int am = tid % BM;
    int ak0 = (tid / BM) * AE;
    int growL = row0 + am;
    int bL = growL >> 9, nL = growL & 511;

    int bRow[BF], bCol[BF];
    #pragma unroll
    for (int s = 0; s < BF; s++) {
        int idx = tid + s * 256;
        bRow[s] = idx / (BN / 4);
        bCol[s] = (idx % (BN / 4)) << 2;
    }

    float aR[AE];
    float4 bR[BF];

    auto ldT = [&](int k0) {
        #pragma unroll
        for (int e = 0; e < AE; e++) {
            int k = k0 + ak0 + e;
            float v = 0.f;
            if (k < K) {
                int j = k / 5;
                int m = k - j * 5;
                if (m == 0) {
                    v = (j < f_in) ? Xa[(long)bL * sb + (long)nL * sn + j]
                                   : Xb[(long)growL * 64 + (j - f_in)];
                } else {
                    long trow = (long)bL * 2048 + (long)(m - 1) * 512 + nL;
                    v = (j < f_in) ? Ta[trow * ldTa + j]
                                   : Tb[trow * ldTb + (j - f_in)];
                }
            }
            aR[e] = v;
        }
        #pragma unroll
        for (int s = 0; s < BF; s++) {
            int k = k0 + bRow[s];
            if (k < K) bR[s] = *(const float4*)(W + (long)k * ldW + col0 + bCol[s]);
            else bR[s] = make_float4(0.f, 0.f, 0.f, 0.f);
        }
    };
    auto stT = [&](int buf) {
        #pragma unroll
        for (int e = 0; e < AE; e++) As[buf][ak0 + e][am] = aR[e];
        #pragma unroll
        for (int s = 0; s < BF; s++) {
            float4 v = bR[s];
            float4 lo = make_float4(v.x, v.x, v.y, v.y);
            float4 hi = make_float4(v.z, v.z, v.w, v.w);
            *(float4*)&BsD[buf][bRow[s]][2 * bCol[s]]     = lo;
            *(float4*)&BsD[buf][bRow[s]][2 * bCol[s] + 4] = hi;
        }
    };

    unsigned long long acc[TM / 2][TN];
    #pragma unroll
    for (int i = 0; i < TM / 2; i++)
        #pragma unroll
        for (int j = 0; j < TN; j++) acc[i][j] = 0ull;

    int ntile = (K + BK - 1) / BK;
    ldT(0); stT(0); __syncthreads();
    for (int t = 0; t < ntile; t++) {
        if (t + 1 < ntile) ldT((t + 1) * BK);
        int buf = t & 1;
        #pragma unroll
        for (int kk = 0; kk < BK; kk++) {
            unsigned long long a2[TM / 2], b2[TN];
            const unsigned long long* ap =
                (const unsigned long long*)&As[buf][kk][ty * TM];
            const unsigned long long* bp =
                (const unsigned long long*)&BsD[buf][kk][2 * tx * TN];
            #pragma unroll
            for (int i = 0; i < TM / 2; i++) a2[i] = ap[i];
            #pragma unroll
            for (int j = 0; j < TN; j++) b2[j] = bp[j];
            #pragma unroll
            for (int i = 0; i < TM / 2; i++)
                #pragma unroll
                for (int j = 0; j < TN; j++) ffma2(acc[i][j], a2[i], b2[j]);
        }
        if (t + 1 < ntile) stT(buf ^ 1);
        __syncthreads();
    }

    #pragma unroll
    for (int i = 0; i < TM / 2; i++) {
        #pragma unroll
        for (int half = 0; half < 2; half++) {
            int grow = row0 + ty * TM + 2 * i + half;
            #pragma unroll
            for (int j = 0; j < TN; j++) {
                int c = col0 + tx * TN + j;
                float v = (half ? f2hi(acc[i][j]) : f2lo(acc[i][j])) + bias[c];
                if (mode == 0) {
                    v = 1.f / (1.f + expf(-v));
                    if (c < 64) RHX[(long)grow * 64 + c] = v * HX[(long)grow * 64 + c];
                    else        Ubuf[(long)grow * 64 + (c - 64)] = v;
                } else {
                    float cc = tanhf(v);
                    float u = Ubuf[(long)grow * 64 + c];
                    float hx = HX[(long)grow * 64 + c];
                    Hout[(long)grow * 64 + c] = u * hx + (1.f - u) * cc;
                }
            }
        }
    }
}

// ---------------------------------------------------------------------------
// Thin diffusion for f_in in {1,2}: T[b, r, c] = sum_j P[b, r, j] * xin[b, j, c]
// ---------------------------------------------------------------------------
__global__ void thin_apply_k(const float* __restrict__ P,
                             const float* __restrict__ xin, long sb, int sn, int f_in,
                             float* __restrict__ T) {
    int gw = (blockIdx.x * blockDim.x + threadIdx.x) >> 5;
    int lane = threadIdx.x & 31;
    if (gw >= B_ * 2048) return;
    int b = gw >> 11, r = gw & 2047;
    const float* Prow = P + ((long)b * 2048 + r) * 512;
    const float* xb = xin + (long)b * sb;
    float a0 = 0.f, a1 = 0.f;
    for (int j = lane; j < 512; j += 32) {
        float p = Prow[j];
        a0 += p * xb[(long)j * sn];
        if (f_in == 2) a1 += p * xb[(long)j * sn + 1];
    }
    #pragma unroll
    for (int o = 16; o; o >>= 1) {
        a0 += __shfl_xor_sync(0xffffffffu, a0, o);
        a1 += __shfl_xor_sync(0xffffffffu, a1, o);
    }
    if (lane == 0) {
        T[(long)gw * f_in] = a0;
        if (f_in == 2) T[(long)gw * f_in + 1] = a1;
    }
}

// ---------------------------------------------------------------------------
// Misc small kernels
// ---------------------------------------------------------------------------
__global__ void add_his_k(float* __restrict__ h0, float* __restrict__ h1,
                          const float* __restrict__ his) {
    int i = blockIdx.x * blockDim.x + threadIdx.x;
    if (i < B_ * N_ * U_) { h0[i] += his[i]; h1[i] += his[i]; }
}

__global__ void proj_k(const float* __restrict__ h, const float* __restrict__ W,
                       const float* __restrict__ bptr, float* __restrict__ decin,
                       float* __restrict__ out, int t) {
    int grow = blockIdx.x * blockDim.x + threadIdx.x;
    if (grow >= B_ * N_) return;
    float s = bptr[0];
    const float* hr = h + (long)grow * 64;
    #pragma unroll
    for (int k = 0; k < 64; k++) s += hr[k] * W[k];
    decin[grow] = s;
    out[(long)grow * HOR + t] = s;
}

// ---------------------------------------------------------------------------
// Host orchestration
// ---------------------------------------------------------------------------
static const int BIG = 1 << 30;

static void diff64(const float* P, const float* X, long sX, float* T) {
    // T[b](2048 x 64) = P[b](2048 x 512) @ X[b](512 x 64)
    dim3 g(1, 16, B_);
    sgemm2_t<128, 64, 8, 4><<<g, 256>>>(512, P, 512, (long)4 * N_ * N_,
                                        X, 64, sX, nullptr, 0, 0, BIG,
                                        T, 64, (long)2048 * 64,
                                        0, nullptr, 0, nullptr);
}

static void diff128(const float* P, const float* X1, long s1,
                    const float* X2, long s2, float* T) {
    // T[b](2048 x 128) = P[b] @ [X1 | X2]
    dim3 g(1, 16, B_);
    sgemm2_t<128, 128, 8, 8><<<g, 256>>>(512, P, 512, (long)4 * N_ * N_,
                                         X1, 64, s1, X2, 64, s2, 64,
                                         T, 128, (long)2048 * 128,
                                         0, nullptr, 0, nullptr);
}

static void cell(float* S, const float* xin, long sb, int sn, int f_in,
                 const float* hx, float* hout,
                 const float* Wg, const float* bg,
                 const float* Wc, const float* bc) {
    float* P    = S + OFF_P;
    float* TCAT = S + OFF_TCAT;
    float* THX  = S + OFF_THX;
    float* TRHX = S + OFF_TRHX;
    float* RHX  = S + OFF_RHX;
    float* Ub   = S + OFF_U;

    int K = (f_in + 64) * 5;
    const long sH = (long)N_ * 64;

    if (f_in == 64) {
        // merged diffusion of [xin | hx] -> TCAT (B,2048,128)
        diff128(P, xin, sb, hx, sH, TCAT);
        catgemm2_t<128, 64, 8, 4><<<dim3(2, 128), 256>>>(
            K, f_in, xin, sb, sn, hx, TCAT, 128, TCAT + 64, 128,
            Wg, 128, bg, hx, RHX, Ub, nullptr, 0);
        diff64(P, RHX, sH, TRHX);
        catgemm2_t<64, 64, 4, 4><<<dim3(1, 256), 256>>>(
            K, f_in, xin, sb, sn, RHX, TCAT, 128, TRHX, 64,
            Wc, 64, bc, hx, nullptr, Ub, hout, 1);
    } else {
        thin_apply_k<<<8192, 256>>>(P, xin, sb, sn, f_in, TCAT);
        diff64(P, hx, sH, THX);
        catgemm2_t<128, 64, 8, 4><<<dim3(2, 128), 256>>>(
            K, f_in, xin, sb, sn, hx, TCAT, f_in, THX, 64,
            Wg, 128, bg, hx, RHX, Ub, nullptr, 0);
        diff64(P, RHX, sH, TRHX);
        catgemm2_t<64, 64, 4, 4><<<dim3(1, 256), 256>>>(
            K, f_in, xin, sb, sn, RHX, TCAT, f_in, TRHX, 64,
            Wc, 64, bc, hx, nullptr, Ub, hout, 1);
    }
}

extern "C" void kernel_launch(void* const* d_in, const int* in_sizes, int n_in,
                              void* d_out, int out_size) {
    (void)in_sizes; (void)n_in; (void)out_size;
    float* S = nullptr;
    cudaGetSymbolAddress((void**)&S, g_scratch);

    const float* hd   = (const float*)d_in[0];
    const float* hs   = (const float*)d_in[1];
    const float* adj  = (const float*)d_in[2];
    const float* e0Wg = (const float*)d_in[3];
    const float* e0bg = (const float*)d_in[4];
    const float* e0Wc = (const float*)d_in[5];
    const float* e0bc = (const float*)d_in[6];
    const float* e1Wg = (const float*)d_in[7];
    const float* e1bg = (const float*)d_in[8];
    const float* e1Wc = (const float*)d_in[9];
    const float* e1bc = (const float*)d_in[10];
    const float* d0Wg = (const float*)d_in[11];
    const float* d0bg = (const float*)d_in[12];
    const float* d0Wc = (const float*)d_in[13];
    const float* d0bc = (const float*)d_in[14];
    const float* d1Wg = (const float*)d_in[15];
    const float* d1bg = (const float*)d_in[16];
    const float* d1Wc = (const float*)d_in[17];
    const float* d1bc = (const float*)d_in[18];
    const float* prW  = (const float*)d_in[19];
    const float* prb  = (const float*)d_in[20];
    const float* f1W  = (const float*)d_in[21];
    const float* f1b  = (const float*)d_in[22];
    const float* f2W  = (const float*)d_in[23];
    const float* f2b  = (const float*)d_in[24];
    float* out = (float*)d_out;

    float* A0  = S + OFF_A0;
    float* A1  = S + OFF_A1;
    float* P   = S + OFF_P;
    float* HIS = S + OFF_HIS;
    float* FC1 = S + OFF_FC1;
    float* DEC = S + OFF_DEC;
    float* RS0 = S + OFF_RS0;
    float* RS1 = S + OFF_RS1;
    float* H[4] = {S + OFF_H0, S + OFF_H1, S + OFF_H2, S + OFF_H3};

    const long HSZ = (long)B_ * N_ * U_;
    cudaMemsetAsync(H[0], 0, HSZ * sizeof(float));
    cudaMemsetAsync(H[1], 0, HSZ * sizeof(float));
    cudaMemsetAsync(DEC, 0, (long)B_ * N_ * sizeof(float));

    // ---- supports + stacked diffusion operator P ----
    rowsum_k<<<(B_ * N_ * 32 + 255) / 256, 256>>>(adj, RS0);
    colsum_k<<<(B_ * N_ + 255) / 256, 256>>>(adj, RS1);
    fill_supports<<<(int)(((long)B_ * N_ * N_ + 255) / 256), 256>>>(adj, RS0, RS1, A0, A1, P);
    const long NB = (long)N_ * N_;
    const long PB = 4 * NB;
    dim3 gp(4, 4, B_);
    // P block m=2: 2*A0@A0 - I
    sgemm2_t<128, 128, 8, 8><<<gp, 256>>>(512, A0, 512, NB, A0, 512, NB,
                                          nullptr, 0, 0, BIG,
                                          P + NB, 512, PB, 1, nullptr, 0, nullptr);
    // P block m=3: A1@A0
    sgemm2_t<128, 128, 8, 8><<<gp, 256>>>(512, A1, 512, NB, A0, 512, NB,
                                          nullptr, 0, 0, BIG,
                                          P + 2 * NB, 512, PB, 0, nullptr, 0, nullptr);
    // P block m=4: 2*A1@(A1A0) - A0
    sgemm2_t<128, 128, 8, 8><<<gp, 256>>>(512, A1, 512, NB, P + 2 * NB, 512, PB,
                                          nullptr, 0, 0, BIG,
                                          P + 3 * NB, 512, PB, 2, A0, NB, nullptr);

    // ---- fc_his ----
    sgemm2_t<128, 128, 8, 8><<<dim3(2, 128, 1), 256>>>(96, hs, 96, 0, f1W, 256, 0,
                                                       nullptr, 0, 0, BIG,
                                                       FC1, 256, 0, 3, nullptr, 0, f1b);
    sgemm2_t<128, 64, 8, 4><<<dim3(1, 128, 1), 256>>>(256, FC1, 256, 0, f2W, 64, 0,
                                                      nullptr, 0, 0, BIG,
                                                      HIS, 64, 0, 3, nullptr, 0, f2b);

    float *hc0 = H[0], *hc1 = H[1], *hn0 = H[2], *hn1 = H[3];

    // ---- encoder ----
    for (int t = 0; t < L_; t++) {
        cell(S, hd + (long)t * N_ * 2, (long)L_ * N_ * 2, 2, 2, hc0, hn0, e0Wg, e0bg, e0Wc, e0bc);
        cell(S, hn0, (long)N_ * U_, U_, 64, hc1, hn1, e1Wg, e1bg, e1Wc, e1bc);
        float* tmp;
        tmp = hc0; hc0 = hn0; hn0 = tmp;
        tmp = hc1; hc1 = hn1; hn1 = tmp;
    }
    add_his_k<<<(int)((HSZ + 255) / 256), 256>>>(hc0, hc1, HIS);

    // ---- decoder ----
    for (int t = 0; t < HOR; t++) {
        cell(S, DEC, (long)N_, 1, 1, hc0, hn0, d0Wg, d0bg, d0Wc, d0bc);
        cell(S, hn0, (long)N_ * U_, U_, 64, hc1, hn1, d1Wg, d1bg, d1Wc, d1bc);
        proj_k<<<(B_ * N_ + 255) / 256, 256>>>(hn1, prW, prb, DEC, out, t);
        float* tmp;
        tmp = hc0; hc0 = hn0; hn0 = tmp;
        tmp = hc1; hc1 = hn1; hn1 = tmp;
    }
}

// round 6
// speedup vs baseline: 1.9576x; 1.9576x over previous
#include <cuda_runtime.h>
#include <math.h>

#define B_  32
#define N_  512
#define L_  12
#define U_  64
#define HOR 12

// ---------------------------------------------------------------------------
// Scratch layout (floats)
// ---------------------------------------------------------------------------
constexpr long SZ_NN  = (long)B_ * N_ * N_;          // 8388608
constexpr long GT     = (long)B_ * N_;               // 16384 (global T-layout row stride)

constexpr long OFF_A0T   = 0;
constexpr long OFF_A1T   = OFF_A0T + SZ_NN;
constexpr long OFF_PT    = OFF_A1T + SZ_NN;              // (B,512,2048)  P^T blocks
constexpr long OFF_TCATT = OFF_PT + 4 * SZ_NN;           // (B,128,2048)
constexpr long OFF_THXT  = OFF_TCATT + (long)B_*128*2048; // (B,64,2048)
constexpr long OFF_TRHXT = OFF_THXT + (long)B_*64*2048;   // (B,64,2048)
constexpr long OFF_TTX   = OFF_TRHXT + (long)B_*64*2048;  // (B,24,2048) enc xin diff
constexpr long OFF_TDEC  = OFF_TTX + (long)B_*24*2048;    // (B,2048)
constexpr long OFF_HISTT = OFF_TDEC + (long)B_*2048;      // (24,16384)
constexpr long OFF_U     = OFF_HISTT + 24*GT;             // (16384,64) row
constexpr long OFF_HIS   = OFF_U + 64*GT;                 // (16384,64) row
constexpr long OFF_FC1   = OFF_HIS + 64*GT;               // (16384,256)
constexpr long OFF_DEC   = OFF_FC1 + 256*GT;              // (16384)
constexpr long OFF_RS0   = OFF_DEC + GT;
constexpr long OFF_RS1   = OFF_RS0 + GT;
constexpr long OFF_RHXT  = OFF_RS1 + GT;                  // (64,16384)
constexpr long OFF_H     = OFF_RHXT + 64*GT;              // 8 buffers x 1M:
// order: h0row,h0T,h1row,h1T,hn0row,hn0T,hn1row,hn1T
constexpr long SZ_H1 = 64*GT;
constexpr long SCRATCH_TOTAL = OFF_H + 8*SZ_H1;

__device__ float g_scratch[SCRATCH_TOTAL];

// ---------------------------------------------------------------------------
// Support construction (transposed supports)
// ---------------------------------------------------------------------------
__global__ void rowsum_k(const float* __restrict__ adj, float* __restrict__ rs0) {
    int w = (blockIdx.x * blockDim.x + threadIdx.x) >> 5;
    int lane = threadIdx.x & 31;
    if (w >= B_ * N_) return;
    const float* base = adj + (long)w * N_;
    float s = 0.f;
    for (int j = lane; j < N_; j += 32) s += base[j];
    #pragma unroll
    for (int o = 16; o; o >>= 1) s += __shfl_xor_sync(0xffffffffu, s, o);
    if (lane == 0) rs0[w] = s + 1.0f;
}

__global__ void colsum_k(const float* __restrict__ adj, float* __restrict__ rs1) {
    int idx = blockIdx.x * blockDim.x + threadIdx.x;
    if (idx >= B_ * N_) return;
    int b = idx >> 9, i = idx & 511;
    const float* base = adj + (long)b * N_ * N_ + i;
    float s = 1.0f;
    for (int j = 0; j < N_; j++) s += base[(long)j * N_];
    rs1[idx] = s;
}

// idx = (b, j, i), i fastest. A0T[j][i] = A0[i][j], A1T[j][i] = A1[i][j].
__global__ void fill_supports_T(const float* __restrict__ adj,
                                const float* __restrict__ rs0,
                                const float* __restrict__ rs1,
                                float* __restrict__ A0T, float* __restrict__ A1T,
                                float* __restrict__ PT) {
    long idx = (long)blockIdx.x * blockDim.x + threadIdx.x;
    if (idx >= (long)B_ * N_ * N_) return;
    int i = (int)(idx & 511);
    long t = idx >> 9;
    int j = (int)(t & 511);
    int b = (int)(t >> 9);
    float d = (i == j) ? 1.f : 0.f;
    float a_ij = adj[((long)b * N_ + i) * N_ + j];   // strided read
    float a_ji = adj[idx];                           // coalesced (adj[b][j][i])
    float v0 = (a_ij + d) / rs0[b * N_ + i];         // A0[i][j]
    float v1 = (a_ji + d) / rs1[b * N_ + i];         // A1[i][j] = (adj[j][i]+d)/rs1[i]
    A0T[idx] = v0;
    A1T[idx] = v1;
    PT[(long)b * 512 * 2048 + (long)j * 2048 + i] = v0;  // block m=1 cols [0,512)
}

// ---------------------------------------------------------------------------
// Generic batched SGEMM (R3 proven): C[b] = A[b] @ B[b], tile BMxBNx16.
// epi: 0 none, 1: 2x - I, 2: 2x - extra[b] (ld 512), 3: bias + relu
// ---------------------------------------------------------------------------
template<int BM, int BN, int TM, int TN>
__global__ __launch_bounds__(256, 2)
void sgemm_t(int K,
             const float* __restrict__ A, int lda, long sA,
             const float* __restrict__ Bm, int ldb, long sB,
             float* __restrict__ C, int ldc, long sC,
             int epi, const float* __restrict__ extra, long sE,
             const float* __restrict__ bias)
{
    constexpr int BK = 16;
    constexpr int TX = BN / TN;
    constexpr int AF = BM / 64;
    constexpr int BF = BN / 64;
    __shared__ float As[2][BK][BM + 4];
    __shared__ float Bs[2][BK][BN];
    int bz = blockIdx.z;
    const float* Ab = A + (long)bz * sA;
    const float* Bb = Bm + (long)bz * sB;
    float* Cb = C + (long)bz * sC;
    int row0 = blockIdx.y * BM, col0 = blockIdx.x * BN;
    int tid = threadIdx.x;
    int tx = tid % TX, ty = tid / TX;

    int aRow[AF], aCol[AF], bRow[BF], bCol[BF];
    #pragma unroll
    for (int s = 0; s < AF; s++) { int idx = tid + s * 256; aRow[s] = idx >> 2; aCol[s] = (idx & 3) << 2; }
    #pragma unroll
    for (int s = 0; s < BF; s++) { int idx = tid + s * 256; bRow[s] = idx / (BN / 4); bCol[s] = (idx % (BN / 4)) << 2; }

    float4 aR[AF], bR[BF];

    auto ldT = [&](int k0) {
        #pragma unroll
        for (int s = 0; s < AF; s++) {
            const float* p = Ab + (long)(row0 + aRow[s]) * lda + k0 + aCol[s];
            if (k0 + BK <= K) aR[s] = *(const float4*)p;
            else {
                int k = k0 + aCol[s];
                aR[s].x = (k     < K) ? p[0] : 0.f;
                aR[s].y = (k + 1 < K) ? p[1] : 0.f;
                aR[s].z = (k + 2 < K) ? p[2] : 0.f;
                aR[s].w = (k + 3 < K) ? p[3] : 0.f;
            }
        }
        #pragma unroll
        for (int s = 0; s < BF; s++) {
            int k = k0 + bRow[s];
            if (k < K) bR[s] = *(const float4*)(Bb + (long)k * ldb + col0 + bCol[s]);
            else bR[s] = make_float4(0.f, 0.f, 0.f, 0.f);
        }
    };
    auto stT = [&](int buf) {
        #pragma unroll
        for (int s = 0; s < AF; s++) {
            As[buf][aCol[s]    ][aRow[s]] = aR[s].x;
            As[buf][aCol[s] + 1][aRow[s]] = aR[s].y;
            As[buf][aCol[s] + 2][aRow[s]] = aR[s].z;
            As[buf][aCol[s] + 3][aRow[s]] = aR[s].w;
        }
        #pragma unroll
        for (int s = 0; s < BF; s++)
            *(float4*)&Bs[buf][bRow[s]][bCol[s]] = bR[s];
    };

    float acc[TM][TN];
    #pragma unroll
    for (int i = 0; i < TM; i++)
        #pragma unroll
        for (int j = 0; j < TN; j++) acc[i][j] = 0.f;

    int ntile = (K + BK - 1) / BK;
    ldT(0); stT(0); __syncthreads();
    for (int t = 0; t < ntile; t++) {
        if (t + 1 < ntile) ldT((t + 1) * BK);
        int buf = t & 1;
        #pragma unroll
        for (int kk = 0; kk < BK; kk++) {
            float ar[TM], br[TN];
            #pragma unroll
            for (int i = 0; i < TM / 4; i++)
                *(float4*)&ar[i * 4] = *(const float4*)&As[buf][kk][ty * TM + i * 4];
            #pragma unroll
            for (int j = 0; j < TN / 4; j++)
                *(float4*)&br[j * 4] = *(const float4*)&Bs[buf][kk][tx * TN + j * 4];
            #pragma unroll
            for (int i = 0; i < TM; i++)
                #pragma unroll
                for (int j = 0; j < TN; j++) acc[i][j] += ar[i] * br[j];
        }
        if (t + 1 < ntile) stT(buf ^ 1);
        __syncthreads();
    }

    #pragma unroll
    for (int i = 0; i < TM; i++) {
        int r = row0 + ty * TM + i;
        #pragma unroll
        for (int j = 0; j < TN; j++) {
            int c = col0 + tx * TN + j;
            float v = acc[i][j];
            if (epi == 1) v = 2.f * v - ((r == c) ? 1.f : 0.f);
            else if (epi == 2) v = 2.f * v - extra[(long)bz * sE + (long)r * N_ + c];
            else if (epi == 3) { v += bias[c]; v = fmaxf(v, 0.f); }
            Cb[(long)r * ldc + c] = v;
        }
    }
}

// ---------------------------------------------------------------------------
// Transposed diffusion GEMM:
//   TT[b](MR x 2048) = Aeff[b](MR x 512) @ PT[b](512 x 2048)
// Aeff row r: r < asplit -> src1[r*16384 + b*512 + k]
//             else (r < MR) -> src2[(r-asplit)*16384 + b*512 + k]
// Row-guarded for MR < gridDim.y*BM (enc precompute MR=24).
// ---------------------------------------------------------------------------
template<int BM, int BN, int TM, int TN>
__global__ __launch_bounds__(256, 2)
void difft_k(int MR, int asplit,
             const float* __restrict__ src1,
             const float* __restrict__ src2,
             const float* __restrict__ PT,
             float* __restrict__ TT, long sT)
{
    constexpr int BK = 16;
    constexpr int TX = BN / TN;
    constexpr int AE = BM * BK / 256;     // floats per thread (contig k)
    constexpr int BF = BK * BN / 1024;
    __shared__ float As[2][BK][BM + 4];
    __shared__ float Bs[2][BK][BN];

    int bz = blockIdx.z;
    int row0 = blockIdx.y * BM, col0 = blockIdx.x * BN;
    int tid = threadIdx.x;
    int tx = tid % TX, ty = tid / TX;

    int am = tid % BM;
    int ak0 = (tid / BM) * AE;
    int r = row0 + am;
    const float* srow = nullptr;
    if (r < asplit) srow = src1 + (long)r * GT + (long)bz * 512;
    else if (r < MR) srow = src2 + (long)(r - asplit) * GT + (long)bz * 512;

    int bRow[BF], bCol[BF];
    #pragma unroll
    for (int s = 0; s < BF; s++) {
        int idx = tid + s * 256;
        bRow[s] = idx / (BN / 4);
        bCol[s] = (idx % (BN / 4)) << 2;
    }

    float aR[AE];
    float4 bR[BF];
    const float* Pb = PT + (long)bz * 512 * 2048;

    auto ldT = [&](int k0) {
        if (srow) {
            #pragma unroll
            for (int e = 0; e < AE; e += 4)
                *(float4*)&aR[e] = *(const float4*)(srow + k0 + ak0 + e);
        } else {
            #pragma unroll
            for (int e = 0; e < AE; e++) aR[e] = 0.f;
        }
        #pragma unroll
        for (int s = 0; s < BF; s++)
            bR[s] = *(const float4*)(Pb + (long)(k0 + bRow[s]) * 2048 + col0 + bCol[s]);
    };
    auto stT = [&](int buf) {
        #pragma unroll
        for (int e = 0; e < AE; e++) As[buf][ak0 + e][am] = aR[e];
        #pragma unroll
        for (int s = 0; s < BF; s++) *(float4*)&Bs[buf][bRow[s]][bCol[s]] = bR[s];
    };

    float acc[TM][TN];
    #pragma unroll
    for (int i = 0; i < TM; i++)
        #pragma unroll
        for (int j = 0; j < TN; j++) acc[i][j] = 0.f;

    constexpr int NT = 512 / BK;
    ldT(0); stT(0); __syncthreads();
    for (int t = 0; t < NT; t++) {
        if (t + 1 < NT) ldT((t + 1) * BK);
        int buf = t & 1;
        #pragma unroll
        for (int kk = 0; kk < BK; kk++) {
            float ar[TM], br[TN];
            #pragma unroll
            for (int i = 0; i < TM / 4; i++)
                *(float4*)&ar[i * 4] = *(const float4*)&As[buf][kk][ty * TM + i * 4];
            #pragma unroll
            for (int j = 0; j < TN / 4; j++)
                *(float4*)&br[j * 4] = *(const float4*)&Bs[buf][kk][tx * TN + j * 4];
            #pragma unroll
            for (int i = 0; i < TM; i++)
                #pragma unroll
                for (int j = 0; j < TN; j++) acc[i][j] += ar[i] * br[j];
        }
        if (t + 1 < NT) stT(buf ^ 1);
        __syncthreads();
    }

    float* Tb = TT + (long)bz * sT;
    #pragma unroll
    for (int i = 0; i < TM; i++) {
        int rr = row0 + ty * TM + i;
        if (rr < MR) {
            #pragma unroll
            for (int j = 0; j < TN; j++) {
                int c = col0 + tx * TN + j;
                Tb[(long)rr * 2048 + c] = acc[i][j];
            }
        }
    }
}

// ---------------------------------------------------------------------------
// Contraction GEMM, transposed (coalesced) A-gather.
// A_eff[row=(b,n), k=j*5+m]:
//   m==0: j<f_in -> Xa[b*sXa + n*snXa + j*sjXa]
//         else   -> XbT[(j-f_in)*16384 + grow]
//   m>=1: off=(m-1)*512+n
//         j<f_in -> Ta[b*sTa + j*2048 + off]
//         else   -> Tb[b*sTb + (j-f_in)*2048 + off]
// mode 0: gate (sigmoid; c<64 -> RHXT = sig*hx; c>=64 -> Urow)
// mode 1: cand (tanh; GRU combine -> HoutT and Hout_row)
// ---------------------------------------------------------------------------
template<int BM, int BN, int TM, int TN>
__global__ __launch_bounds__(256, 2)
void catgemmT_k(int K, int f_in,
                const float* __restrict__ Xa, long sXa, int snXa, long sjXa,
                const float* __restrict__ XbT,
                const float* __restrict__ Ta, long sTa,
                const float* __restrict__ Tb, long sTb,
                const float* __restrict__ W, int ldW,
                const float* __restrict__ bias,
                const float* __restrict__ HXrow,
                const float* __restrict__ Urow,
                float* __restrict__ RHXT, float* __restrict__ Uout,
                float* __restrict__ HoutT, float* __restrict__ HoutR,
                int mode)
{
    constexpr int BK = 16;
    constexpr int TX = BN / TN;
    constexpr int AE = BM * BK / 256;
    constexpr int BF = BK * BN / 1024;
    __shared__ float As[2][BK][BM + 4];
    __shared__ float Bs[2][BK][BN];

    int row0 = blockIdx.y * BM;
    int col0 = blockIdx.x * BN;
    int tid = threadIdx.x;
    int tx = tid % TX, ty = tid / TX;

    int am = tid % BM;
    int ak0 = (tid / BM) * AE;
    int growL = row0 + am;
    int bL = growL >> 9, nL = growL & 511;

    int bRow[BF], bCol[BF];
    #pragma unroll
    for (int s = 0; s < BF; s++) {
        int idx = tid + s * 256;
        bRow[s] = idx / (BN / 4);
        bCol[s] = (idx % (BN / 4)) << 2;
    }

    float aR[AE];
    float4 bR[BF];

    auto ldT = [&](int k0) {
        #pragma unroll
        for (int e = 0; e < AE; e++) {
            int k = k0 + ak0 + e;
            float v = 0.f;
            if (k < K) {
                int j = k / 5;
                int m = k - j * 5;
                if (m == 0) {
                    v = (j < f_in) ? Xa[(long)bL * sXa + (long)nL * snXa + (long)j * sjXa]
                                   : XbT[(long)(j - f_in) * GT + growL];
                } else {
                    long off = (long)(m - 1) * 512 + nL;
                    v = (j < f_in) ? Ta[(long)bL * sTa + (long)j * 2048 + off]
                                   : Tb[(long)bL * sTb + (long)(j - f_in) * 2048 + off];
                }
            }
            aR[e] = v;
        }
        #pragma unroll
        for (int s = 0; s < BF; s++) {
            int k = k0 + bRow[s];
            if (k < K) bR[s] = *(const float4*)(W + (long)k * ldW + col0 + bCol[s]);
            else bR[s] = make_float4(0.f, 0.f, 0.f, 0.f);
        }
    };
    auto stT = [&](int buf) {
        #pragma unroll
        for (int e = 0; e < AE; e++) As[buf][ak0 + e][am] = aR[e];
        #pragma unroll
        for (int s = 0; s < BF; s++) *(float4*)&Bs[buf][bRow[s]][bCol[s]] = bR[s];
    };

    float acc[TM][TN];
    #pragma unroll
    for (int i = 0; i < TM; i++)
        #pragma unroll
        for (int j = 0; j < TN; j++) acc[i][j] = 0.f;

    int ntile = (K + BK - 1) / BK;
    ldT(0); stT(0); __syncthreads();
    for (int t = 0; t < ntile; t++) {
        if (t + 1 < ntile) ldT((t + 1) * BK);
        int buf = t & 1;
        #pragma unroll
        for (int kk = 0; kk < BK; kk++) {
            float ar[TM], br[TN];
            #pragma unroll
            for (int i = 0; i < TM / 4; i++)
                *(float4*)&ar[i * 4] = *(const float4*)&As[buf][kk][ty * TM + i * 4];
            #pragma unroll
            for (int j = 0; j < TN / 4; j++)
                *(float4*)&br[j * 4] = *(const float4*)&Bs[buf][kk][tx * TN + j * 4];
            #pragma unroll
            for (int i = 0; i < TM; i++)
                #pragma unroll
                for (int j = 0; j < TN; j++) acc[i][j] += ar[i] * br[j];
        }
        if (t + 1 < ntile) stT(buf ^ 1);
        __syncthreads();
    }

    #pragma unroll
    for (int i = 0; i < TM; i++) {
        int grow = row0 + ty * TM + i;
        #pragma unroll
        for (int j = 0; j < TN; j++) {
            int c = col0 + tx * TN + j;
            float v = acc[i][j] + bias[c];
            if (mode == 0) {
                v = 1.f / (1.f + expf(-v));
                if (c < 64) RHXT[(long)c * GT + grow] = v * HXrow[(long)grow * 64 + c];
                else        Uout[(long)grow * 64 + (c - 64)] = v;
            } else {
                float cc = tanhf(v);
                float u = Urow[(long)grow * 64 + c];
                float hx = HXrow[(long)grow * 64 + c];
                float h = u * hx + (1.f - u) * cc;
                HoutT[(long)c * GT + grow] = h;
                HoutR[(long)grow * 64 + c] = h;
            }
        }
    }
}

// ---------------------------------------------------------------------------
// Small kernels
// ---------------------------------------------------------------------------
// histT[(t*2+c)][b*512+n] = hd[b][t][n][c]
__global__ void hist_t_k(const float* __restrict__ hd, float* __restrict__ histT) {
    int idx = blockIdx.x * blockDim.x + threadIdx.x;   // (row, b, n): n fastest
    if (idx >= 24 * B_ * N_) return;
    int n = idx & 511;
    int t2 = idx >> 9;
    int b = t2 & 31;
    int row = t2 >> 5;           // 0..23
    int t = row >> 1, c = row & 1;
    histT[(long)row * GT + b * 512 + n] =
        hd[(((long)b * L_ + t) * N_ + n) * 2 + c];
}

// TDEC[b][r] = sum_j DEC[b*512+j] * PT[b][j][r]
__global__ void dec_diff_k(const float* __restrict__ PT,
                           const float* __restrict__ dec,
                           float* __restrict__ TDEC) {
    int b = blockIdx.y;
    int r = blockIdx.x * 256 + threadIdx.x;
    __shared__ float ds[512];
    ds[threadIdx.x] = dec[b * 512 + threadIdx.x];
    ds[threadIdx.x + 256] = dec[b * 512 + threadIdx.x + 256];
    __syncthreads();
    const float* p = PT + (long)b * 512 * 2048 + r;
    float acc = 0.f;
    #pragma unroll 8
    for (int j = 0; j < 512; j++) acc += ds[j] * p[(long)j * 2048];
    TDEC[(long)b * 2048 + r] = acc;
}

__global__ void add_his_k(float* __restrict__ h0r, float* __restrict__ h0T,
                          float* __restrict__ h1r, float* __restrict__ h1T,
                          const float* __restrict__ his) {
    int i = blockIdx.x * blockDim.x + threadIdx.x;
    if (i >= B_ * N_ * U_) return;
    int grow = i >> 6, c = i & 63;
    float v = his[i];
    h0r[i] += v; h1r[i] += v;
    h0T[(long)c * GT + grow] += v;
    h1T[(long)c * GT + grow] += v;
}

__global__ void projT_k(const float* __restrict__ hT, const float* __restrict__ W,
                        const float* __restrict__ bptr, float* __restrict__ decin,
                        float* __restrict__ out, int t) {
    int grow = blockIdx.x * blockDim.x + threadIdx.x;
    if (grow >= B_ * N_) return;
    float s = bptr[0];
    #pragma unroll
    for (int c = 0; c < 64; c++) s += hT[(long)c * GT + grow] * W[c];
    decin[grow] = s;
    out[(long)grow * HOR + t] = s;
}

// ---------------------------------------------------------------------------
// Host orchestration
// ---------------------------------------------------------------------------
struct HPair { float* r; float* t; };

static void diff128(const float* src1, const float* src2, const float* PT, float* TT) {
    difft_k<128, 64, 8, 4><<<dim3(32, 1, B_), 256>>>(128, 64, src1, src2, TT ? PT : PT, TT, (long)128 * 2048);
}
static void diff64(const float* src1, const float* PT, float* TT) {
    difft_k<64, 64, 4, 4><<<dim3(32, 1, B_), 256>>>(64, 64, src1, nullptr, PT, TT, (long)64 * 2048);
}

// One GRU cell (transposed dataflow).
static void cell(float* S, int f_in,
                 const float* Xa, long sXa, int snXa, long sjXa,  // xin (m=0,j<f_in)
                 const float* xinT_for_diff,    // (f_in==64) layer-1 xin in T layout
                 const float* Ta, long sTa,     // diffusion of xin
                 HPair hx, HPair hout,
                 const float* Wg, const float* bg,
                 const float* Wc, const float* bc) {
    float* PT    = S + OFF_PT;
    float* TCATT = S + OFF_TCATT;
    float* THXT  = S + OFF_THXT;
    float* TRHXT = S + OFF_TRHXT;
    float* RHXT  = S + OFF_RHXT;
    float* Ub    = S + OFF_U;

    int K = (f_in + 64) * 5;
    const float* TaG;  long sTaG;
    const float* TbG;  long sTbG;

    if (f_in == 64) {
        // merged diffusion of [xinT ; hxT] -> TCATT (B,128,2048)
        difft_k<128, 64, 8, 4><<<dim3(32, 1, B_), 256>>>(
            128, 64, xinT_for_diff, hx.t, PT, TCATT, (long)128 * 2048);
        TaG = TCATT;             sTaG = (long)128 * 2048;
        TbG = TCATT + 64 * 2048; sTbG = (long)128 * 2048;
    } else {
        diff64(hx.t, PT, THXT);
        TaG = Ta;   sTaG = sTa;
        TbG = THXT; sTbG = (long)64 * 2048;
    }

    // gate
    catgemmT_k<128, 64, 8, 4><<<dim3(2, 128), 256>>>(
        K, f_in, Xa, sXa, snXa, sjXa, hx.t, TaG, sTaG, TbG, sTbG,
        Wg, 128, bg, hx.r, nullptr, RHXT, Ub, nullptr, nullptr, 0);

    // diffusion of r*hx
    diff64(RHXT, PT, TRHXT);

    // candidate + GRU combine
    catgemmT_k<64, 64, 4, 4><<<dim3(1, 256), 256>>>(
        K, f_in, Xa, sXa, snXa, sjXa, RHXT, TaG, sTaG, TRHXT, (long)64 * 2048,
        Wc, 64, bc, hx.r, Ub, nullptr, nullptr, hout.t, hout.r, 1);
}

extern "C" void kernel_launch(void* const* d_in, const int* in_sizes, int n_in,
                              void* d_out, int out_size) {
    (void)in_sizes; (void)n_in; (void)out_size;
    float* S = nullptr;
    cudaGetSymbolAddress((void**)&S, g_scratch);

    const float* hd   = (const float*)d_in[0];
    const float* hs   = (const float*)d_in[1];
    const float* adj  = (const float*)d_in[2];
    const float* e0Wg = (const float*)d_in[3];
    const float* e0bg = (const float*)d_in[4];
    const float* e0Wc = (const float*)d_in[5];
    const float* e0bc = (const float*)d_in[6];
    const float* e1Wg = (const float*)d_in[7];
    const float* e1bg = (const float*)d_in[8];
    const float* e1Wc = (const float*)d_in[9];
    const float* e1bc = (const float*)d_in[10];
    const float* d0Wg = (const float*)d_in[11];
    const float* d0bg = (const float*)d_in[12];
    const float* d0Wc = (const float*)d_in[13];
    const float* d0bc = (const float*)d_in[14];
    const float* d1Wg = (const float*)d_in[15];
    const float* d1bg = (const float*)d_in[16];
    const float* d1Wc = (const float*)d_in[17];
    const float* d1bc = (const float*)d_in[18];
    const float* prW  = (const float*)d_in[19];
    const float* prb  = (const float*)d_in[20];
    const float* f1W  = (const float*)d_in[21];
    const float* f1b  = (const float*)d_in[22];
    const float* f2W  = (const float*)d_in[23];
    const float* f2b  = (const float*)d_in[24];
    float* out = (float*)d_out;

    float* A0T  = S + OFF_A0T;
    float* A1T  = S + OFF_A1T;
    float* PT   = S + OFF_PT;
    float* TTX  = S + OFF_TTX;
    float* TDEC = S + OFF_TDEC;
    float* HISTT= S + OFF_HISTT;
    float* HIS  = S + OFF_HIS;
    float* FC1  = S + OFF_FC1;
    float* DEC  = S + OFF_DEC;
    float* RS0  = S + OFF_RS0;
    float* RS1  = S + OFF_RS1;

    HPair H[4], HN[4];
    for (int i = 0; i < 4; i++) {
        H[i].r  = S + OFF_H + (2 * i) * SZ_H1;
        H[i].t  = S + OFF_H + (2 * i + 1) * SZ_H1;
    }
    // H[0]=h0 cur, H[1]=h1 cur, H[2]=h0 next, H[3]=h1 next

    cudaMemsetAsync(S + OFF_H, 0, 4 * SZ_H1 * sizeof(float));   // h0,h1 (row+T)
    cudaMemsetAsync(DEC, 0, (long)B_ * N_ * sizeof(float));

    // ---- supports + transposed stacked diffusion operator PT ----
    rowsum_k<<<(B_ * N_ * 32 + 255) / 256, 256>>>(adj, RS0);
    colsum_k<<<(B_ * N_ + 255) / 256, 256>>>(adj, RS1);
    fill_supports_T<<<(int)(((long)B_ * N_ * N_ + 255) / 256), 256>>>(adj, RS0, RS1, A0T, A1T, PT);
    const long NB = (long)N_ * N_;
    const long PB = (long)512 * 2048;
    dim3 gp(4, 4, B_);
    // PT block m=2 (cols 512..1024): 2*A0T@A0T - I
    sgemm_t<128, 128, 8, 8><<<gp, 256>>>(512, A0T, 512, NB, A0T, 512, NB,
                                         PT + 512, 2048, PB, 1, nullptr, 0, nullptr);
    // PT block m=3 (cols 1024..1536): A0T@A1T
    sgemm_t<128, 128, 8, 8><<<gp, 256>>>(512, A0T, 512, NB, A1T, 512, NB,
                                         PT + 1024, 2048, PB, 0, nullptr, 0, nullptr);
    // PT block m=4 (cols 1536..2048): 2*(PTm3)@A1T - A0T
    sgemm_t<128, 128, 8, 8><<<gp, 256>>>(512, PT + 1024, 2048, PB, A1T, 512, NB,
                                         PT + 1536, 2048, PB, 2, A0T, NB, nullptr);

    // ---- fc_his ----
    sgemm_t<128, 128, 8, 8><<<dim3(2, 128, 1), 256>>>(96, hs, 96, 0, f1W, 256, 0,
                                                      FC1, 256, 0, 3, nullptr, 0, f1b);
    sgemm_t<128, 64, 8, 4><<<dim3(1, 128, 1), 256>>>(256, FC1, 256, 0, f2W, 64, 0,
                                                     HIS, 64, 0, 3, nullptr, 0, f2b);

    // ---- encoder layer-0 input diffusions, all timesteps at once ----
    hist_t_k<<<(24 * B_ * N_ + 255) / 256, 256>>>(hd, HISTT);
    difft_k<64, 64, 4, 4><<<dim3(32, 1, B_), 256>>>(24, 24, HISTT, nullptr, PT,
                                                    TTX, (long)24 * 2048);

    HPair hc0 = H[0], hc1 = H[1], hn0 = H[2], hn1 = H[3];

    // ---- encoder ----
    for (int t = 0; t < L_; t++) {
        // layer 0: f_in=2, xin from hd, Ta = TTX rows (t*2, t*2+1)
        cell(S, 2,
             hd + (long)t * N_ * 2, (long)L_ * N_ * 2, 2, 1,
             nullptr,
             TTX + (long)t * 2 * 2048, (long)24 * 2048,
             hc0, hn0, e0Wg, e0bg, e0Wc, e0bc);
        // layer 1: f_in=64, xin = hn0 (T layout), Xa strides: sjXa=GT
        cell(S, 64,
             hn0.t, 512, 1, (long)GT,
             hn0.t, nullptr, 0,
             hc1, hn1, e1Wg, e1bg, e1Wc, e1bc);
        HPair tmp;
        tmp = hc0; hc0 = hn0; hn0 = tmp;
        tmp = hc1; hc1 = hn1; hn1 = tmp;
    }
    add_his_k<<<(B_ * N_ * U_ + 255) / 256, 256>>>(hc0.r, hc0.t, hc1.r, hc1.t, HIS);

    // ---- decoder ----
    for (int t = 0; t < HOR; t++) {
        // layer 0: f_in=1, xin = DEC
        dec_diff_k<<<dim3(8, B_), 256>>>(PT, DEC, TDEC);
        cell(S, 1,
             DEC, 512, 1, 0,
             nullptr,
             TDEC, (long)2048,
             hc0, hn0, d0Wg, d0bg, d0Wc, d0bc);
        // layer 1
        cell(S, 64,
             hn0.t, 512, 1, (long)GT,
             hn0.t, nullptr, 0,
             hc1, hn1, d1Wg, d1bg, d1Wc, d1bc);
        projT_k<<<(B_ * N_ + 255) / 256, 256>>>(hn1.t, prW, prb, DEC, out, t);
        HPair tmp;
        tmp = hc0; hc0 = hn0; hn0 = tmp;
        tmp = hc1; hc1 = hn1; hn1 = tmp;
    }
}